// round 1
// baseline (speedup 1.0000x reference)
#include <cuda_runtime.h>
#include <cstdint>
#include <cstddef>

// Problem constants
#define NB    8
#define NCH   256
#define NTOK  4096                 // H*W = 64*64
#define CHB   ((size_t)NCH * NTOK) // per-batch elems of a [C, N] tensor
#define NNB   ((size_t)NTOK * NTOK)

// Static scratch (allocation APIs are forbidden; __device__ globals are the
// sanctioned mechanism).
__device__ float g_hn[NB * CHB];   // groupnorm output, later reused for att@V output
__device__ float g_q [NB * CHB];
__device__ float g_k [NB * CHB];
__device__ float g_v [NB * CHB];
__device__ float g_s [NB * NNB];   // attention logits / probs (537 MB)

// ---------------------------------------------------------------------------
// GroupNorm: one block per (batch, group). G=32 groups, 8 channels/group,
// 8*4096 = 32768 elems per group.
// ---------------------------------------------------------------------------
__global__ __launch_bounds__(256) void groupnorm_kernel(
    const float* __restrict__ x, const float* __restrict__ sc,
    const float* __restrict__ bi, float* __restrict__ out)
{
    int b = blockIdx.x >> 5;
    int g = blockIdx.x & 31;
    size_t base = ((size_t)b * NCH + (size_t)g * 8) * NTOK;
    const float4* px = (const float4*)(x + base);
    float4* po = (float4*)(out + base);
    int t = threadIdx.x;

    float s = 0.f, ss = 0.f;
#pragma unroll
    for (int r = 0; r < 32; r++) {
        float4 f = px[r * 256 + t];
        s  += f.x + f.y + f.z + f.w;
        ss += f.x * f.x + f.y * f.y + f.z * f.z + f.w * f.w;
    }
#pragma unroll
    for (int o = 16; o; o >>= 1) {
        s  += __shfl_xor_sync(0xffffffffu, s, o);
        ss += __shfl_xor_sync(0xffffffffu, ss, o);
    }
    __shared__ float rs[8], rss[8];
    __shared__ float s_mean, s_rstd;
    if ((t & 31) == 0) { rs[t >> 5] = s; rss[t >> 5] = ss; }
    __syncthreads();
    if (t == 0) {
        float S = 0.f, SS = 0.f;
#pragma unroll
        for (int i = 0; i < 8; i++) { S += rs[i]; SS += rss[i]; }
        float m = S * (1.f / 32768.f);
        float var = SS * (1.f / 32768.f) - m * m;
        s_mean = m;
        s_rstd = rsqrtf(var + 1e-6f);
    }
    __syncthreads();
    float m = s_mean, rstd = s_rstd;
#pragma unroll
    for (int r = 0; r < 32; r++) {
        int idx = r * 256 + t;          // float4 index within 8192
        int c = g * 8 + (idx >> 10);    // 1024 float4 per channel
        float a = sc[c] * rstd;
        float bb = bi[c] - m * a;
        float4 f = px[idx];
        po[idx] = make_float4(f.x * a + bb, f.y * a + bb, f.z * a + bb, f.w * a + bb);
    }
}

// ---------------------------------------------------------------------------
// Batched GEMM: C[z] = outscale * (alpha * op(A[z]) * op(B[z]) + bias + resid)
//   A_KMAJOR=1: A is [K][M] (K-major rows of length M)  -> A[k*ldA + m]
//   A_KMAJOR=0: A is [M][K] row-major                   -> A[m*ldA + k]
//   B_TRANS=0 : B is [K][N]                             -> B[k*ldB + n]
//   B_TRANS=1 : B is [N][K] row-major                   -> B[n*ldB + k]
// 128x128 tile, BK=8, 256 threads, 8x8 per thread, register prefetch.
// All dims divide tile sizes exactly for this problem -> no bounds checks.
// ---------------------------------------------------------------------------
#define BM 128
#define BN 128
#define BK 8
#define ASTR 132

template<int A_KMAJOR, int B_TRANS, int HAS_BIAS, int RESID>
__global__ __launch_bounds__(256) void gemm128(
    const float* __restrict__ A, const float* __restrict__ B,
    float* __restrict__ C, const float* __restrict__ bias,
    const float* __restrict__ resid,
    int M, int N, int K, float alpha, float outscale,
    size_t batchA, size_t batchB, size_t batchC)
{
    __shared__ float as[BK * ASTR];
    __shared__ float bs[BK * ASTR];

    int t  = threadIdx.x;
    int tx = t & 15, ty = t >> 4;
    int m0 = blockIdx.y * BM, n0 = blockIdx.x * BN;
    size_t z = blockIdx.z;
    A += z * batchA;
    B += z * batchB;

    int ldA = A_KMAJOR ? M : K;
    int ldB = B_TRANS ? K : N;

    float acc[8][8];
#pragma unroll
    for (int i = 0; i < 8; i++)
#pragma unroll
        for (int j = 0; j < 8; j++) acc[i][j] = 0.f;

    const int nch = K / BK;
    float4 aReg, bReg;

    // prefetch chunk 0
    if (A_KMAJOR) {
        aReg = *(const float4*)&A[(size_t)((t >> 5)) * ldA + m0 + (t & 31) * 4];
    } else {
        aReg = *(const float4*)&A[(size_t)(m0 + (t >> 1)) * ldA + (t & 1) * 4];
    }
    if (!B_TRANS) {
        bReg = *(const float4*)&B[(size_t)((t >> 5)) * ldB + n0 + (t & 31) * 4];
    } else {
        bReg = *(const float4*)&B[(size_t)(n0 + (t >> 1)) * ldB + (t & 1) * 4];
    }

    for (int kt = 0; kt < nch; kt++) {
        // stage registers -> smem
        if (A_KMAJOR) {
            *(float4*)&as[(t >> 5) * ASTR + (t & 31) * 4] = aReg;
        } else {
            int i = t >> 1, kb = (t & 1) * 4;
            as[(kb + 0) * ASTR + i] = aReg.x;
            as[(kb + 1) * ASTR + i] = aReg.y;
            as[(kb + 2) * ASTR + i] = aReg.z;
            as[(kb + 3) * ASTR + i] = aReg.w;
        }
        if (!B_TRANS) {
            *(float4*)&bs[(t >> 5) * ASTR + (t & 31) * 4] = bReg;
        } else {
            int j = t >> 1, kb = (t & 1) * 4;
            bs[(kb + 0) * ASTR + j] = bReg.x;
            bs[(kb + 1) * ASTR + j] = bReg.y;
            bs[(kb + 2) * ASTR + j] = bReg.z;
            bs[(kb + 3) * ASTR + j] = bReg.w;
        }
        __syncthreads();

        // prefetch next chunk (global loads overlap compute)
        if (kt + 1 < nch) {
            int kofs = (kt + 1) * BK;
            if (A_KMAJOR) {
                aReg = *(const float4*)&A[(size_t)(kofs + (t >> 5)) * ldA + m0 + (t & 31) * 4];
            } else {
                aReg = *(const float4*)&A[(size_t)(m0 + (t >> 1)) * ldA + kofs + (t & 1) * 4];
            }
            if (!B_TRANS) {
                bReg = *(const float4*)&B[(size_t)(kofs + (t >> 5)) * ldB + n0 + (t & 31) * 4];
            } else {
                bReg = *(const float4*)&B[(size_t)(n0 + (t >> 1)) * ldB + kofs + (t & 1) * 4];
            }
        }

#pragma unroll
        for (int kk = 0; kk < BK; kk++) {
            float a[8], b[8];
            *(float4*)&a[0] = *(const float4*)&as[kk * ASTR + ty * 8];
            *(float4*)&a[4] = *(const float4*)&as[kk * ASTR + ty * 8 + 4];
            *(float4*)&b[0] = *(const float4*)&bs[kk * ASTR + tx * 8];
            *(float4*)&b[4] = *(const float4*)&bs[kk * ASTR + tx * 8 + 4];
#pragma unroll
            for (int i = 0; i < 8; i++)
#pragma unroll
                for (int j = 0; j < 8; j++) acc[i][j] = fmaf(a[i], b[j], acc[i][j]);
        }
        __syncthreads();
    }

    // epilogue
    int mb = m0 + ty * 8, nb = n0 + tx * 8;
#pragma unroll
    for (int i = 0; i < 8; i++) {
        int m = mb + i;
        float bv = HAS_BIAS ? bias[m] : 0.f;
        size_t cbase = z * batchC + (size_t)m * N + nb;
#pragma unroll
        for (int jj = 0; jj < 2; jj++) {
            float4 o;
            o.x = acc[i][jj * 4 + 0] * alpha + bv;
            o.y = acc[i][jj * 4 + 1] * alpha + bv;
            o.z = acc[i][jj * 4 + 2] * alpha + bv;
            o.w = acc[i][jj * 4 + 3] * alpha + bv;
            if (RESID) {
                float4 rv = *(const float4*)&resid[cbase + jj * 4];
                o.x = (o.x + rv.x) * outscale;
                o.y = (o.y + rv.y) * outscale;
                o.z = (o.z + rv.z) * outscale;
                o.w = (o.w + rv.w) * outscale;
            } else if (outscale != 1.f) {
                o.x *= outscale; o.y *= outscale; o.z *= outscale; o.w *= outscale;
            }
            *(float4*)&C[cbase + jj * 4] = o;
        }
    }
}

// ---------------------------------------------------------------------------
// Row softmax over 4096-wide rows, in place. One block per row.
// ---------------------------------------------------------------------------
__global__ __launch_bounds__(256) void softmax_kernel(float* __restrict__ s)
{
    size_t row = blockIdx.x;
    float4* p = (float4*)(s + row * (size_t)NTOK);
    int t = threadIdx.x;

    float4 v[4];
    float mx = -3.0e38f;
#pragma unroll
    for (int r = 0; r < 4; r++) {
        v[r] = p[r * 256 + t];
        mx = fmaxf(mx, fmaxf(fmaxf(v[r].x, v[r].y), fmaxf(v[r].z, v[r].w)));
    }
#pragma unroll
    for (int o = 16; o; o >>= 1) mx = fmaxf(mx, __shfl_xor_sync(0xffffffffu, mx, o));
    __shared__ float red[8];
    if ((t & 31) == 0) red[t >> 5] = mx;
    __syncthreads();
#pragma unroll
    for (int i = 0; i < 8; i++) mx = fmaxf(mx, red[i]);
    __syncthreads();

    float sum = 0.f;
#pragma unroll
    for (int r = 0; r < 4; r++) {
        v[r].x = __expf(v[r].x - mx);
        v[r].y = __expf(v[r].y - mx);
        v[r].z = __expf(v[r].z - mx);
        v[r].w = __expf(v[r].w - mx);
        sum += v[r].x + v[r].y + v[r].z + v[r].w;
    }
#pragma unroll
    for (int o = 16; o; o >>= 1) sum += __shfl_xor_sync(0xffffffffu, sum, o);
    if ((t & 31) == 0) red[t >> 5] = sum;
    __syncthreads();
    float tot = 0.f;
#pragma unroll
    for (int i = 0; i < 8; i++) tot += red[i];
    float inv = 1.f / tot;
#pragma unroll
    for (int r = 0; r < 4; r++) {
        v[r].x *= inv; v[r].y *= inv; v[r].z *= inv; v[r].w *= inv;
        p[r * 256 + t] = v[r];
    }
}

// ---------------------------------------------------------------------------
// kernel_launch
// inputs: x, gn_scale, gn_bias, w_q, b_q, w_k, b_k, w_v, b_v, w_o, b_o
// ---------------------------------------------------------------------------
extern "C" void kernel_launch(void* const* d_in, const int* in_sizes, int n_in,
                              void* d_out, int out_size)
{
    const float* x   = (const float*)d_in[0];
    const float* gns = (const float*)d_in[1];
    const float* gnb = (const float*)d_in[2];
    const float* wq  = (const float*)d_in[3];
    const float* bq  = (const float*)d_in[4];
    const float* wk  = (const float*)d_in[5];
    const float* bk  = (const float*)d_in[6];
    const float* wv  = (const float*)d_in[7];
    const float* bv  = (const float*)d_in[8];
    const float* wo  = (const float*)d_in[9];
    const float* bo  = (const float*)d_in[10];
    float* out = (float*)d_out;

    float* hn = g_hn;
    float* q  = g_q;
    float* k  = g_k;
    float* v  = g_v;
    float* s  = g_s;

    // 1) GroupNorm
    groupnorm_kernel<<<NB * 32, 256>>>(x, gns, gnb, hn);

    // 2) q/k/v projections: C[o][n] = W[o][c] * hn[c][n] + b  (M=256,N=4096,K=256)
    dim3 gp(NTOK / BN, NCH / BM, NB);
    gemm128<0, 0, 1, 0><<<gp, 256>>>(wq, hn, q, bq, nullptr,
                                     NCH, NTOK, NCH, 1.f, 1.f, 0, CHB, CHB);
    gemm128<0, 0, 1, 0><<<gp, 256>>>(wk, hn, k, bk, nullptr,
                                     NCH, NTOK, NCH, 1.f, 1.f, 0, CHB, CHB);
    gemm128<0, 0, 1, 0><<<gp, 256>>>(wv, hn, v, bv, nullptr,
                                     NCH, NTOK, NCH, 1.f, 1.f, 0, CHB, CHB);

    // 3) logits: s[n][m] = scale * sum_c q[c][n]*k[c][m]  (M=N=4096, K=256)
    dim3 gs(NTOK / BN, NTOK / BM, NB);
    gemm128<1, 0, 0, 0><<<gs, 256>>>(q, k, s, nullptr, nullptr,
                                     NTOK, NTOK, NCH, 0.0625f, 1.f, CHB, CHB, NNB);

    // 4) softmax over m (rows of s)
    softmax_kernel<<<NB * NTOK, 256>>>(s);

    // 5) attn output: ao[c][n] = sum_m v[c][m] * att[n][m]  (M=256,N=4096,K=4096)
    //    write into g_hn (no longer needed)
    dim3 gav(NTOK / BN, NCH / BM, NB);
    gemm128<0, 1, 0, 0><<<gav, 256>>>(v, s, hn, nullptr, nullptr,
                                      NCH, NTOK, NTOK, 1.f, 1.f, CHB, NNB, CHB);

    // 6) output projection + residual + /sqrt(2)
    gemm128<0, 0, 1, 1><<<gp, 256>>>(wo, hn, out, bo, x,
                                     NCH, NTOK, NCH, 1.f, 0.70710678118654752f, 0, CHB, CHB);
}